// round 13
// baseline (speedup 1.0000x reference)
#include <cuda_runtime.h>
#include <math.h>

#define B_ 2
#define T_ 512
#define C_ 263
#define D_ 512
#define F_ 257          // T/2 + 1
#define K_TOP 51        // int(512 * 0.1)
#define WIN_ 24
#define KPAD 288        // 263 padded to multiple of 32 (zero-filled)

// packed spectrum: row f in [0,256] = re_f ; row 256+f for f in [1,255] = im_f
#define MR 512
#define KI 512
#define NDELTA 128      // max masked packed rows (<=102), padded

// ---------------- scratch (static device memory; no allocation) ----------------
__device__ float g_ex [B_*T_*D_];
__device__ float g_h  [B_*T_*D_];
__device__ float g_mtd[B_*T_*D_];
__device__ float g_cf [B_*MR*D_];
__device__ float g_delta[B_*NDELTA*D_];     // (token - cf) at masked packed rows
__device__ float g_wsub [B_*T_*NDELTA];     // gathered Widft columns
__device__ int   g_rowlist[B_*NDELTA];
__device__ float g_score[B_*T_];
__device__ float g_mag  [B_*F_];
__device__ int   g_tidx[B_*K_TOP];
__device__ int   g_fidx[B_*K_TOP];
__device__ unsigned char g_tmask[B_*T_];
__device__ unsigned char g_fmask[B_*F_];
__device__ unsigned char g_tm   [B_*T_];
__device__ float g_costab[512];
__device__ float g_sintab[512];
__device__ float g_pe[T_*D_];
__device__ double g_div[256];
__device__ float g_xpad[B_*T_*KPAD + 64];
__device__ float g_wpad[D_*KPAD + 64];
__device__ float g_wdft [MR*T_];
__device__ float g_widft[T_*KI];

// ---------------- streams/events (created in static ctor, pre-checkpoint) ------
static cudaStream_t g_sB = nullptr, g_sC = nullptr;
static cudaEvent_t g_evStart = nullptr, g_evFork = nullptr;
static cudaEvent_t g_evJoin = nullptr, g_evC = nullptr;
namespace {
struct StreamInit {
    StreamInit() {
        cudaStreamCreateWithFlags(&g_sB, cudaStreamNonBlocking);
        cudaStreamCreateWithFlags(&g_sC, cudaStreamNonBlocking);
        cudaEventCreateWithFlags(&g_evStart, cudaEventDisableTiming);
        cudaEventCreateWithFlags(&g_evFork, cudaEventDisableTiming);
        cudaEventCreateWithFlags(&g_evJoin, cudaEventDisableTiming);
        cudaEventCreateWithFlags(&g_evC, cudaEventDisableTiming);
    }
};
StreamInit g_streamInit;
}

// ---------------- table init ----------------------------------------------------
__global__ void init_div_kernel() {
    int i = threadIdx.x;
    if (i < 256) {
        g_div[i] = exp(-(double)(2 * i) * (9.210340371976184 / 512.0));
    }
    if (i < 512) {
        float s, c;
        sincospif((float)i / 256.0f, &s, &c);
        g_costab[i] = c; g_sintab[i] = s;
    }
}

// merged: PE table + pad x -> [B*T][288] + pad W_emb -> [D][288]
__global__ void prep_kernel(const float* __restrict__ x, const float* __restrict__ w) {
    int i = blockIdx.x * blockDim.x + threadIdx.x;
    const int nPE = T_ * D_;
    const int nX  = B_ * T_ * KPAD;
    if (i < nPE) {
        int t = i / D_, d = i % D_;
        double arg = (double)t * g_div[d >> 1];
        const double PI2 = 6.283185307179586476925286766559;
        double q = rint(arg * (1.0 / PI2));
        float rf = (float)(arg - q * PI2);
        g_pe[i] = (d & 1) ? cosf(rf) : sinf(rf);
    } else if (i < nPE + nX) {
        int j = i - nPE;
        int r = j / KPAD, c = j % KPAD;
        g_xpad[j] = (c < C_) ? x[r * C_ + c] : 0.f;
    } else {
        int j = i - nPE - nX;
        if (j < D_ * KPAD) {
            int r = j / KPAD, c = j % KPAD;
            g_wpad[j] = (c < C_) ? w[r * C_ + c] : 0.f;
        }
    }
}

// DFT weight tables (input-independent; identical twiddle values)
__global__ void init_wdft_kernel() {
    int i = blockIdx.x * blockDim.x + threadIdx.x;
    const int n1 = MR * T_;
    if (i < n1) {
        int r = i >> 9, t = i & 511;
        float s, c;
        if (r <= 256) {
            sincospif((float)((r * t) & 511) / 256.0f, &s, &c);
            g_wdft[i] = c;
        } else {
            sincospif((float)(((r - 256) * t) & 511) / 256.0f, &s, &c);
            g_wdft[i] = -s;
        }
    } else {
        int j = i - n1;
        if (j < T_ * KI) {
            int t = j >> 9, c = j & 511;
            float s, cc;
            if (c <= 256) {
                float w = (c == 0 || c == 256) ? (1.f / 512.f) : (2.f / 512.f);
                sincospif((float)((c * t) & 511) / 256.0f, &s, &cc);
                g_widft[j] = w * cc;
            } else {
                int f = c - 256;
                sincospif((float)((f * t) & 511) / 256.0f, &s, &cc);
                g_widft[j] = -(2.f / 512.f) * s;
            }
        }
    }
}

// ---------------- epilogue ids --------------------------------------------------
#define EPI_NONE    0
#define EPI_PE      2
#define EPI_GELU    3
#define EPI_SIGMASK 4
#define EPI_TMSEL   5
#define EPI_ADDEX   6

__device__ __forceinline__ float apply_epi(int EPI, float v, int row, int col, int N,
        int zb,
        const float* __restrict__ bias,
        const unsigned char* __restrict__ mask,
        const float* __restrict__ token,
        const float* __restrict__ e1, const float* __restrict__ e2,
        const float* __restrict__ e3, const float* __restrict__ e4)
{
    if (EPI == EPI_PE) {
        v += bias[col];
        v += g_pe[(row & (T_ - 1)) * D_ + col];
    } else if (EPI == EPI_GELU) {
        v += bias[col];
        v = 0.5f * v * (1.f + erff(v * 0.70710678118654752f));
    } else if (EPI == EPI_SIGMASK) {
        v += bias[col];
        v = 1.f / (1.f + expf(-v));
        if (mask[row]) v = token[col];
    } else if (EPI == EPI_TMSEL) {
        if (col < N && !mask[row]) {
            float m = v, a = 0.f;
            for (int dd = 0; dd < D_; dd++) {
                float u = fmaf(m, e1[dd], e2[dd]);
                float g = 0.5f * u * (1.f + erff(u * 0.70710678118654752f));
                a = fmaf(g, e3[dd], a);
            }
            v = 1.f / (1.f + expf(-(a + e4[0])));
        }
    } else if (EPI == EPI_ADDEX) {
        v += g_ex[((long)zb * T_ + row) * D_ + col];
    }
    return v;
}

// ---------------- SGEMM v6 (solo ex): 64m x 32n x 32k, 128 thr, 2 blk/SM -------
template <int EPI, int BKN>
__global__ void __launch_bounds__(128, 2) sgemm6_kernel(
        const float* __restrict__ A, int lda, long sA,
        const float* __restrict__ B, int ldb, long sB,
        float* __restrict__ Cm, int ldc, long sC, int N, int K,
        const float* __restrict__ bias,
        const unsigned char* __restrict__ mask,
        const float* __restrict__ token,
        const float* __restrict__ e1, const float* __restrict__ e2,
        const float* __restrict__ e3, const float* __restrict__ e4)
{
    A += (long)blockIdx.z * sA;
    B += (long)blockIdx.z * sB;
    Cm += (long)blockIdx.z * sC;
    __shared__ float As[2][32][64];
    __shared__ float Bs[2][32][32];
    int tid = threadIdx.x;            // 128
    int bm = blockIdx.y * 64;
    int bn = blockIdx.x * 32;
    int tx = (tid & 7) * 4;
    int ty = (tid >> 3) * 4;
    int arow = tid >> 1, akq = (tid & 1) * 16;   // A: 4 quads/thread
    int brow = tid >> 2, bkq = (tid & 3) * 8;    // B^T: 2 quads/thread
    int bkk  = tid >> 2, bnn = (tid & 3) * 8;    // BKN=1 B: 2 quads/thread
    float acc[4][4] = {};
    float4 ra[4], rb[2];

    #pragma unroll
    for (int j = 0; j < 4; j++)
        ra[j] = *(const float4*)&A[(size_t)(bm + arow) * lda + akq + j * 4];
    if (BKN) {
        #pragma unroll
        for (int j = 0; j < 2; j++) {
            rb[j] = make_float4(0.f, 0.f, 0.f, 0.f);
            if (bn + bnn + j * 4 < ldb)
                rb[j] = *(const float4*)&B[(size_t)bkk * ldb + bn + bnn + j * 4];
        }
    } else {
        #pragma unroll
        for (int j = 0; j < 2; j++)
            rb[j] = *(const float4*)&B[(size_t)(bn + brow) * ldb + bkq + j * 4];
    }
    #pragma unroll
    for (int j = 0; j < 4; j++) {
        As[0][akq + j * 4 + 0][arow] = ra[j].x; As[0][akq + j * 4 + 1][arow] = ra[j].y;
        As[0][akq + j * 4 + 2][arow] = ra[j].z; As[0][akq + j * 4 + 3][arow] = ra[j].w;
    }
    if (BKN) {
        #pragma unroll
        for (int j = 0; j < 2; j++)
            *(float4*)&Bs[0][bkk][bnn + j * 4] = rb[j];
    } else {
        #pragma unroll
        for (int j = 0; j < 2; j++) {
            Bs[0][bkq + j * 4 + 0][brow] = rb[j].x; Bs[0][bkq + j * 4 + 1][brow] = rb[j].y;
            Bs[0][bkq + j * 4 + 2][brow] = rb[j].z; Bs[0][bkq + j * 4 + 3][brow] = rb[j].w;
        }
    }
    __syncthreads();

    int p = 0;
    for (int k0 = 32; ; k0 += 32) {
        bool has_next = (k0 < K);
        if (has_next) {
            #pragma unroll
            for (int j = 0; j < 4; j++)
                ra[j] = *(const float4*)&A[(size_t)(bm + arow) * lda + k0 + akq + j * 4];
            if (BKN) {
                #pragma unroll
                for (int j = 0; j < 2; j++) {
                    rb[j] = make_float4(0.f, 0.f, 0.f, 0.f);
                    if (bn + bnn + j * 4 < ldb)
                        rb[j] = *(const float4*)&B[(size_t)(k0 + bkk) * ldb + bn + bnn + j * 4];
                }
            } else {
                #pragma unroll
                for (int j = 0; j < 2; j++)
                    rb[j] = *(const float4*)&B[(size_t)(bn + brow) * ldb + k0 + bkq + j * 4];
            }
        }
        #pragma unroll
        for (int kk = 0; kk < 32; kk++) {
            float4 a = *(const float4*)&As[p][kk][ty];
            float4 b = *(const float4*)&Bs[p][kk][tx];
            float am[4] = {a.x, a.y, a.z, a.w};
            float bv[4] = {b.x, b.y, b.z, b.w};
            #pragma unroll
            for (int i = 0; i < 4; i++)
                #pragma unroll
                for (int j = 0; j < 4; j++)
                    acc[i][j] = fmaf(am[i], bv[j], acc[i][j]);
        }
        if (!has_next) break;
        int q = p ^ 1;
        #pragma unroll
        for (int j = 0; j < 4; j++) {
            As[q][akq + j * 4 + 0][arow] = ra[j].x; As[q][akq + j * 4 + 1][arow] = ra[j].y;
            As[q][akq + j * 4 + 2][arow] = ra[j].z; As[q][akq + j * 4 + 3][arow] = ra[j].w;
        }
        if (BKN) {
            #pragma unroll
            for (int j = 0; j < 2; j++)
                *(float4*)&Bs[q][bkk][bnn + j * 4] = rb[j];
        } else {
            #pragma unroll
            for (int j = 0; j < 2; j++) {
                Bs[q][bkq + j * 4 + 0][brow] = rb[j].x; Bs[q][bkq + j * 4 + 1][brow] = rb[j].y;
                Bs[q][bkq + j * 4 + 2][brow] = rb[j].z; Bs[q][bkq + j * 4 + 3][brow] = rb[j].w;
            }
        }
        __syncthreads();
        p = q;
    }

    const bool vec = ((N & 3) == 0);
    #pragma unroll
    for (int i = 0; i < 4; i++) {
        int row = bm + ty + i;
        float v4[4];
        #pragma unroll
        for (int j = 0; j < 4; j++) {
            int col = bn + tx + j;
            v4[j] = apply_epi(EPI, acc[i][j], row, col, N, blockIdx.z,
                              bias, mask, token, e1, e2, e3, e4);
        }
        if (vec) {
            *(float4*)&Cm[(size_t)row * ldc + bn + tx] =
                make_float4(v4[0], v4[1], v4[2], v4[3]);
        } else {
            #pragma unroll
            for (int j = 0; j < 4; j++) {
                int col = bn + tx + j;
                if (col < N) Cm[(size_t)row * ldc + col] = v4[j];
            }
        }
    }
}

// ---------------- SGEMM v8 (overlapped): 64m x 64n x 32k, 128 thr, 8x4/thread --
// Higher FFMA:smem ratio (32 FMA per 3 LDS.128; a-frag broadcast across n-threads)
template <int EPI, int BKN>
__global__ void __launch_bounds__(128, 2) sgemm8_kernel(
        const float* __restrict__ A, int lda, long sA,
        const float* __restrict__ B, int ldb, long sB,
        float* __restrict__ Cm, int ldc, long sC, int N, int K,
        const float* __restrict__ bias,
        const unsigned char* __restrict__ mask,
        const float* __restrict__ token,
        const float* __restrict__ e1, const float* __restrict__ e2,
        const float* __restrict__ e3, const float* __restrict__ e4)
{
    A += (long)blockIdx.z * sA;
    B += (long)blockIdx.z * sB;
    Cm += (long)blockIdx.z * sC;
    __shared__ float As[2][32][64];
    __shared__ float Bs[2][32][64];
    int tid = threadIdx.x;            // 128
    int bm = blockIdx.y * 64;
    int bn = blockIdx.x * 64;
    int tx = (tid & 15) * 4;          // n offset 0..60
    int ty = (tid >> 4) * 8;          // m offset 0..56
    int arow = tid >> 1, akq = (tid & 1) * 16;   // A: 4 quads/thread (64 rows x 32 k)
    int brow = tid >> 1, bkq = (tid & 1) * 16;   // B^T: 4 quads (64 rows x 32 k)
    int bkk  = tid >> 2, bnn = (tid & 3) * 16;   // BKN=1 B: 4 quads (32 k x 64 n)
    float acc[8][4] = {};
    float4 ra[4], rb[4];

    // prologue: tile 0 -> buffer 0
    #pragma unroll
    for (int j = 0; j < 4; j++)
        ra[j] = *(const float4*)&A[(size_t)(bm + arow) * lda + akq + j * 4];
    if (BKN) {
        #pragma unroll
        for (int j = 0; j < 4; j++) {
            rb[j] = make_float4(0.f, 0.f, 0.f, 0.f);
            if (bn + bnn + j * 4 < ldb)
                rb[j] = *(const float4*)&B[(size_t)bkk * ldb + bn + bnn + j * 4];
        }
    } else {
        #pragma unroll
        for (int j = 0; j < 4; j++)
            rb[j] = *(const float4*)&B[(size_t)(bn + brow) * ldb + bkq + j * 4];
    }
    #pragma unroll
    for (int j = 0; j < 4; j++) {
        As[0][akq + j * 4 + 0][arow] = ra[j].x; As[0][akq + j * 4 + 1][arow] = ra[j].y;
        As[0][akq + j * 4 + 2][arow] = ra[j].z; As[0][akq + j * 4 + 3][arow] = ra[j].w;
    }
    if (BKN) {
        #pragma unroll
        for (int j = 0; j < 4; j++)
            *(float4*)&Bs[0][bkk][bnn + j * 4] = rb[j];
    } else {
        #pragma unroll
        for (int j = 0; j < 4; j++) {
            Bs[0][bkq + j * 4 + 0][brow] = rb[j].x; Bs[0][bkq + j * 4 + 1][brow] = rb[j].y;
            Bs[0][bkq + j * 4 + 2][brow] = rb[j].z; Bs[0][bkq + j * 4 + 3][brow] = rb[j].w;
        }
    }
    __syncthreads();

    int p = 0;
    for (int k0 = 32; ; k0 += 32) {
        bool has_next = (k0 < K);
        if (has_next) {
            #pragma unroll
            for (int j = 0; j < 4; j++)
                ra[j] = *(const float4*)&A[(size_t)(bm + arow) * lda + k0 + akq + j * 4];
            if (BKN) {
                #pragma unroll
                for (int j = 0; j < 4; j++) {
                    rb[j] = make_float4(0.f, 0.f, 0.f, 0.f);
                    if (bn + bnn + j * 4 < ldb)
                        rb[j] = *(const float4*)&B[(size_t)(k0 + bkk) * ldb + bn + bnn + j * 4];
                }
            } else {
                #pragma unroll
                for (int j = 0; j < 4; j++)
                    rb[j] = *(const float4*)&B[(size_t)(bn + brow) * ldb + k0 + bkq + j * 4];
            }
        }
        #pragma unroll
        for (int kk = 0; kk < 32; kk++) {
            float4 a0 = *(const float4*)&As[p][kk][ty];
            float4 a1 = *(const float4*)&As[p][kk][ty + 4];
            float4 b  = *(const float4*)&Bs[p][kk][tx];
            float am[8] = {a0.x, a0.y, a0.z, a0.w, a1.x, a1.y, a1.z, a1.w};
            float bv[4] = {b.x, b.y, b.z, b.w};
            #pragma unroll
            for (int i = 0; i < 8; i++)
                #pragma unroll
                for (int j = 0; j < 4; j++)
                    acc[i][j] = fmaf(am[i], bv[j], acc[i][j]);
        }
        if (!has_next) break;
        int q = p ^ 1;
        #pragma unroll
        for (int j = 0; j < 4; j++) {
            As[q][akq + j * 4 + 0][arow] = ra[j].x; As[q][akq + j * 4 + 1][arow] = ra[j].y;
            As[q][akq + j * 4 + 2][arow] = ra[j].z; As[q][akq + j * 4 + 3][arow] = ra[j].w;
        }
        if (BKN) {
            #pragma unroll
            for (int j = 0; j < 4; j++)
                *(float4*)&Bs[q][bkk][bnn + j * 4] = rb[j];
        } else {
            #pragma unroll
            for (int j = 0; j < 4; j++) {
                Bs[q][bkq + j * 4 + 0][brow] = rb[j].x; Bs[q][bkq + j * 4 + 1][brow] = rb[j].y;
                Bs[q][bkq + j * 4 + 2][brow] = rb[j].z; Bs[q][bkq + j * 4 + 3][brow] = rb[j].w;
            }
        }
        __syncthreads();
        p = q;
    }

    const bool vec = ((N & 3) == 0);
    #pragma unroll
    for (int i = 0; i < 8; i++) {
        int row = bm + ty + i;
        float v4[4];
        #pragma unroll
        for (int j = 0; j < 4; j++) {
            int col = bn + tx + j;
            v4[j] = apply_epi(EPI, acc[i][j], row, col, N, blockIdx.z,
                              bias, mask, token, e1, e2, e3, e4);
        }
        if (vec) {
            *(float4*)&Cm[(size_t)row * ldc + bn + tx] =
                make_float4(v4[0], v4[1], v4[2], v4[3]);
        } else {
            #pragma unroll
            for (int j = 0; j < 4; j++) {
                int col = bn + tx + j;
                if (col < N) Cm[(size_t)row * ldc + col] = v4[j];
            }
        }
    }
}

// ---------------- windowed-variance score: one block per (b,t) -----------------
__global__ void score_kernel() {
    int bt = blockIdx.x;
    int b = bt >> 9, t = bt & 511;
    int tid = threadIdx.x;            // 256
    int t0 = t - (WIN_ - 1); if (t0 < 0) t0 = 0;
    float denom = (float)((t + 1 < WIN_) ? (t + 1) : WIN_);
    float num = 0.f, den = 0.f;
    for (int d = tid; d < D_; d += 256) {
        float s1 = 0.f, s2 = 0.f;
        const float* p = &g_ex[((size_t)b * T_ + t0) * D_ + d];
        for (int tt = t0; tt <= t; tt++) {
            float v = *p; p += D_;
            s1 += v;
            s2 = fmaf(v, v, s2);
        }
        float m1 = s1 / denom;
        num += s2 / denom - m1 * m1;
        den += m1;
    }
    __shared__ float sn[256], sd[256];
    sn[tid] = num; sd[tid] = den; __syncthreads();
    for (int s = 128; s > 0; s >>= 1) {
        if (tid < s) { sn[tid] += sn[tid + s]; sd[tid] += sd[tid + s]; }
        __syncthreads();
    }
    if (tid == 0) g_score[bt] = sn[0] / (sd[0] + 1e-6f);
}

// ---------------- top-k via rank selection (lax.top_k stable-desc semantics) ---
__global__ void topk_kernel(const float* __restrict__ vals, int n, int k,
                            int* __restrict__ idx_out,
                            unsigned char* __restrict__ mask_out,
                            float* __restrict__ outf)
{
    int b = blockIdx.x;
    int tid = threadIdx.x;            // 512
    __shared__ float v[512];
    for (int i = tid; i < n; i += blockDim.x) v[i] = vals[b * n + i];
    if (tid < n) mask_out[b * n + tid] = 0;
    __syncthreads();
    if (tid < n) {
        float x = v[tid];
        int rank = 0;
        for (int j = 0; j < n; j++) {
            float y = v[j];
            rank += (y > x) || (y == x && j < tid);
        }
        if (rank < k) {
            idx_out[b * k + rank] = tid;
            outf[b * k + rank] = (float)tid;
            mask_out[b * n + tid] = 1;
        }
    }
}

// ---------------- magnitude mean over d: one block per (b,f) -------------------
__global__ void mag_kernel() {
    int bf = blockIdx.x;
    int b = bf / F_, f = bf % F_;
    int d = threadIdx.x;              // 512
    float cr = g_cf[((size_t)b * MR + f) * D_ + d];
    float ci = (f == 0 || f == 256) ? 0.f
             : g_cf[((size_t)b * MR + 256 + f) * D_ + d];
    float m = sqrtf(cr * cr + ci * ci);
    __shared__ float red[512];
    red[d] = m; __syncthreads();
    for (int s = 256; s > 0; s >>= 1) {
        if (d < s) red[d] += red[d + s];
        __syncthreads();
    }
    if (d == 0) g_mag[bf] = red[0] * (1.f / 512.f);
}

// ---------------- fused: freq top-k + tm mask + compacted masked-row list ------
__global__ void freqpost_kernel(float* __restrict__ out_fidx) {
    int b = blockIdx.x;
    int tid = threadIdx.x;            // 512
    __shared__ float v[512];
    if (tid < F_) v[tid] = g_mag[b * F_ + tid];
    if (tid < F_) g_fmask[b * F_ + tid] = 0;
    if (tid < NDELTA) g_rowlist[b * NDELTA + tid] = -1;
    __syncthreads();
    if (tid < F_) {
        float x = v[tid];
        int rank = 0;
        for (int j = 0; j < F_; j++) {
            float y = v[j];
            rank += (y > x) || (y == x && j < tid);
        }
        if (rank < K_TOP) {
            g_fidx[b * K_TOP + rank] = tid;
            out_fidx[b * K_TOP + rank] = (float)tid;
            g_fmask[b * F_ + tid] = 1;
        }
    }
    __syncthreads();
    {
        const unsigned char* fm = &g_fmask[b * F_];
        int t = tid;
        float y = fm[0] ? 1.f : 0.f;
        for (int f = 1; f < 256; f++)
            if (fm[f]) y += 2.f * g_costab[(f * t) & 511];
        if (fm[256]) y += (t & 1) ? -1.f : 1.f;
        g_tm[b * T_ + t] = (y != 0.f) ? 1 : 0;
    }
    if (tid < F_ && g_fmask[b * F_ + tid]) {
        int f = tid;
        int rank = 0;
        for (int g2 = 0; g2 < f; g2++)
            if (g_fmask[b * F_ + g2]) rank += (g2 == 0 || g2 == 256) ? 1 : 2;
        g_rowlist[b * NDELTA + rank] = f;               // re row
        if (f >= 1 && f <= 255)
            g_rowlist[b * NDELTA + rank + 1] = 256 + f; // im row
    }
}

// ---------------- build delta (token - cf, masked rows) + gathered Widft cols --
__global__ void builddw_kernel(const float* __restrict__ f_tok_re,
                               const float* __restrict__ f_tok_im) {
    int i = blockIdx.x * blockDim.x + threadIdx.x;
    const int nD = B_ * NDELTA * D_;
    if (i < nD) {
        int b = i / (NDELTA * D_);
        int rem = i - b * NDELTA * D_;
        int j = rem >> 9, d = rem & 511;
        int r = g_rowlist[b * NDELTA + j];
        float v = 0.f;
        if (r >= 0) {
            float tok = (r <= 256) ? f_tok_re[d] : f_tok_im[d];
            v = tok - g_cf[((size_t)b * MR + r) * D_ + d];
        }
        g_delta[i] = v;
    } else {
        int k = i - nD;
        if (k < B_ * T_ * NDELTA) {
            int b = k / (T_ * NDELTA);
            int rem = k - b * T_ * NDELTA;
            int t = rem / NDELTA, j = rem % NDELTA;
            int r = g_rowlist[b * NDELTA + j];
            g_wsub[k] = (r >= 0) ? g_widft[t * KI + r] : 0.f;
        }
    }
}

// ---------------- launch ----------------
extern "C" void kernel_launch(void* const* d_in, const int* in_sizes, int n_in,
                              void* d_out, int out_size) {
    const float* x        = (const float*)d_in[0];
    const float* W_emb    = (const float*)d_in[1];
    const float* b_emb    = (const float*)d_in[2];
    const float* t_token  = (const float*)d_in[3];
    const float* tW1      = (const float*)d_in[4];
    const float* tb1      = (const float*)d_in[5];
    const float* tW2      = (const float*)d_in[6];
    const float* tb2      = (const float*)d_in[7];
    const float* f_tok_re = (const float*)d_in[8];
    const float* f_tok_im = (const float*)d_in[9];
    const float* fW1      = (const float*)d_in[10];
    const float* fb1      = (const float*)d_in[11];
    const float* fW2      = (const float*)d_in[12];
    const float* fb2      = (const float*)d_in[13];
    float* out = (float*)d_out;

    // output packing: out_t [B,T,D] | tidx [B,51] | out_f [B,T,C] | fidx [B,51]
    float* out_t    = out;
    float* out_tidx = out + (size_t)B_ * T_ * D_;
    float* out_f    = out_tidx + B_ * K_TOP;
    float* out_fidx = out_f + (size_t)B_ * T_ * C_;

    float *p_ex, *p_h, *p_mtd, *p_score, *p_xpad, *p_wpad;
    float *p_wdft, *p_widft, *p_cf, *p_delta, *p_wsub;
    int *p_tidx;
    unsigned char *p_tmask, *p_tm;
    cudaGetSymbolAddress((void**)&p_ex,    g_ex);
    cudaGetSymbolAddress((void**)&p_h,     g_h);
    cudaGetSymbolAddress((void**)&p_mtd,   g_mtd);
    cudaGetSymbolAddress((void**)&p_score, g_score);
    cudaGetSymbolAddress((void**)&p_xpad,  g_xpad);
    cudaGetSymbolAddress((void**)&p_wpad,  g_wpad);
    cudaGetSymbolAddress((void**)&p_wdft,  g_wdft);
    cudaGetSymbolAddress((void**)&p_widft, g_widft);
    cudaGetSymbolAddress((void**)&p_cf,    g_cf);
    cudaGetSymbolAddress((void**)&p_delta, g_delta);
    cudaGetSymbolAddress((void**)&p_wsub,  g_wsub);
    cudaGetSymbolAddress((void**)&p_tidx,  g_tidx);
    cudaGetSymbolAddress((void**)&p_tmask, g_tmask);
    cudaGetSymbolAddress((void**)&p_tm,    g_tm);

    if (!g_sB) {
        cudaStreamCreateWithFlags(&g_sB, cudaStreamNonBlocking);
        cudaStreamCreateWithFlags(&g_sC, cudaStreamNonBlocking);
        cudaEventCreateWithFlags(&g_evStart, cudaEventDisableTiming);
        cudaEventCreateWithFlags(&g_evFork, cudaEventDisableTiming);
        cudaEventCreateWithFlags(&g_evJoin, cudaEventDisableTiming);
        cudaEventCreateWithFlags(&g_evC, cudaEventDisableTiming);
    }

    // ---- legal capture fork at t=0 ----
    cudaEventRecord(g_evStart, 0);
    cudaStreamWaitEvent(g_sB, g_evStart, 0);

    // DFT weight tables on g_sB (input-independent; overlaps prologue + GEMM1)
    init_wdft_kernel<<<(MR * T_ + T_ * KI + 255) / 256, 256, 0, g_sB>>>();

    // ---- prologue on stream 0 ----
    init_div_kernel<<<1, 512>>>();
    prep_kernel<<<(T_ * D_ + (B_ * T_ + D_) * KPAD + 255) / 256, 256>>>(x, W_emb);

    // ex = x * W_emb^T + b_emb + PE      (padded K=288; solo -> sgemm6, grid 256)
    sgemm6_kernel<EPI_PE, 0><<<dim3(D_ / 32, B_ * T_ / 64), 128>>>(
        p_xpad, KPAD, 0, p_wpad, KPAD, 0, p_ex, D_, 0, D_, KPAD,
        b_emb, nullptr, nullptr, nullptr, nullptr, nullptr, nullptr);

    // ---- fork after ex ----
    cudaEventRecord(g_evFork, 0);
    cudaStreamWaitEvent(g_sB, g_evFork, 0);
    cudaStreamWaitEvent(g_sC, g_evFork, 0);

    // ---- path C: score + temporal top-k (overlaps h-GEMM) ----
    score_kernel<<<B_ * T_, 256, 0, g_sC>>>();
    topk_kernel<<<B_, 512, 0, g_sC>>>(p_score, T_, K_TOP, p_tidx, p_tmask, out_tidx);
    cudaEventRecord(g_evC, g_sC);

    // ---- path B (frequency) on g_sB ----
    {
        // cf[b] = Wdft[512,512] @ ex[b][512,512]   (packed re/im rows)
        sgemm8_kernel<EPI_NONE, 1><<<dim3(D_ / 64, MR / 64, B_), 128, 0, g_sB>>>(
            p_wdft, T_, 0, p_ex, D_, (long)T_ * D_, p_cf, D_, (long)MR * D_, D_, T_,
            nullptr, nullptr, nullptr, nullptr, nullptr, nullptr, nullptr);
        mag_kernel<<<B_ * F_, 512, 0, g_sB>>>();
        freqpost_kernel<<<B_, 512, 0, g_sB>>>(out_fidx);
        builddw_kernel<<<(B_ * NDELTA * D_ + B_ * T_ * NDELTA + 255) / 256, 256, 0, g_sB>>>(
            f_tok_re, f_tok_im);
        // mtd[b] = ex[b] + Wsub[b][512,128] @ delta[b][128,512]
        sgemm8_kernel<EPI_ADDEX, 1><<<dim3(D_ / 64, T_ / 64, B_), 128, 0, g_sB>>>(
            p_wsub, NDELTA, (long)T_ * NDELTA,
            p_delta, D_, (long)NDELTA * D_,
            p_mtd, D_, (long)T_ * D_, D_, NDELTA,
            nullptr, nullptr, nullptr, nullptr, nullptr, nullptr, nullptr);
        // out_f = tmsel(mtd @ W_emb)   (fused mx + outf)
        sgemm8_kernel<EPI_TMSEL, 1><<<dim3((C_ + 63) / 64, B_ * T_ / 64), 128, 0, g_sB>>>(
            p_mtd, D_, 0, p_wpad, KPAD, 0, out_f, C_, 0, C_, D_,
            nullptr, p_tm, nullptr, fW1, fb1, fW2, fb2);
        cudaEventRecord(g_evJoin, g_sB);
    }

    // ---- path A (temporal GEMMs) on stream 0 ----
    // h = gelu(ex * tW1^T + tb1)   — independent of score/topk
    sgemm8_kernel<EPI_GELU, 0><<<dim3(D_ / 64, B_ * T_ / 64), 128>>>(
        p_ex, D_, 0, tW1, D_, 0, p_h, D_, 0, D_, D_,
        tb1, nullptr, nullptr, nullptr, nullptr, nullptr, nullptr);
    // out_t = tmask ? t_token : sigmoid(h * tW2^T + tb2)  — needs tmask from path C
    cudaStreamWaitEvent(0, g_evC, 0);
    sgemm8_kernel<EPI_SIGMASK, 0><<<dim3(D_ / 64, B_ * T_ / 64), 128>>>(
        p_h, D_, 0, tW2, D_, 0, out_t, D_, 0, D_, D_,
        tb2, p_tmask, t_token, nullptr, nullptr, nullptr, nullptr);

    // ---- join ----
    cudaStreamWaitEvent(0, g_evJoin, 0);
}

// round 14
// speedup vs baseline: 1.1472x; 1.1472x over previous
#include <cuda_runtime.h>
#include <math.h>

#define B_ 2
#define T_ 512
#define C_ 263
#define D_ 512
#define F_ 257          // T/2 + 1
#define K_TOP 51        // int(512 * 0.1)
#define WIN_ 24
#define KPAD 288        // 263 padded to multiple of 32 (zero-filled)

// packed spectrum: row f in [0,256] = re_f ; row 256+f for f in [1,255] = im_f
#define MR 512
#define KI 512
#define NDELTA 128      // max masked packed rows (<=102), padded

// ---------------- scratch (static device memory; no allocation) ----------------
__device__ float g_ex [B_*T_*D_];
__device__ float g_h  [B_*T_*D_];
__device__ float g_mtd[B_*T_*D_];
__device__ float g_cf [B_*MR*D_];
__device__ float g_delta[B_*NDELTA*D_];     // (token - cf) at masked packed rows
__device__ float g_wsub [B_*T_*NDELTA];     // gathered Widft columns
__device__ int   g_rowlist[B_*NDELTA];
__device__ float g_score[B_*T_];
__device__ float g_mag  [B_*F_];
__device__ int   g_tidx[B_*K_TOP];
__device__ int   g_fidx[B_*K_TOP];
__device__ unsigned char g_tmask[B_*T_];
__device__ unsigned char g_fmask[B_*F_];
__device__ unsigned char g_tm   [B_*T_];
__device__ float g_costab[512];
__device__ float g_sintab[512];
__device__ float g_pe[T_*D_];
__device__ double g_div[256];
__device__ float g_xpad[B_*T_*KPAD + 64];
__device__ float g_wpad[D_*KPAD + 64];
__device__ float g_wdft [MR*T_];
__device__ float g_widft[T_*KI];

// ---------------- streams/events (created in static ctor, pre-checkpoint) ------
static cudaStream_t g_sB = nullptr, g_sC = nullptr;
static cudaEvent_t g_evStart = nullptr, g_evFork = nullptr;
static cudaEvent_t g_evJoin = nullptr, g_evC = nullptr;
namespace {
struct StreamInit {
    StreamInit() {
        cudaStreamCreateWithFlags(&g_sB, cudaStreamNonBlocking);
        cudaStreamCreateWithFlags(&g_sC, cudaStreamNonBlocking);
        cudaEventCreateWithFlags(&g_evStart, cudaEventDisableTiming);
        cudaEventCreateWithFlags(&g_evFork, cudaEventDisableTiming);
        cudaEventCreateWithFlags(&g_evJoin, cudaEventDisableTiming);
        cudaEventCreateWithFlags(&g_evC, cudaEventDisableTiming);
    }
};
StreamInit g_streamInit;
}

// ---------------- table init ----------------------------------------------------
__global__ void init_div_kernel() {
    int i = threadIdx.x;
    if (i < 256) {
        g_div[i] = exp(-(double)(2 * i) * (9.210340371976184 / 512.0));
    }
    if (i < 512) {
        float s, c;
        sincospif((float)i / 256.0f, &s, &c);
        g_costab[i] = c; g_sintab[i] = s;
    }
}

// merged: PE table + pad x -> [B*T][288] + pad W_emb -> [D][288]
__global__ void prep_kernel(const float* __restrict__ x, const float* __restrict__ w) {
    int i = blockIdx.x * blockDim.x + threadIdx.x;
    const int nPE = T_ * D_;
    const int nX  = B_ * T_ * KPAD;
    if (i < nPE) {
        int t = i / D_, d = i % D_;
        double arg = (double)t * g_div[d >> 1];
        const double PI2 = 6.283185307179586476925286766559;
        double q = rint(arg * (1.0 / PI2));
        float rf = (float)(arg - q * PI2);
        g_pe[i] = (d & 1) ? cosf(rf) : sinf(rf);
    } else if (i < nPE + nX) {
        int j = i - nPE;
        int r = j / KPAD, c = j % KPAD;
        g_xpad[j] = (c < C_) ? x[r * C_ + c] : 0.f;
    } else {
        int j = i - nPE - nX;
        if (j < D_ * KPAD) {
            int r = j / KPAD, c = j % KPAD;
            g_wpad[j] = (c < C_) ? w[r * C_ + c] : 0.f;
        }
    }
}

// DFT weight tables (input-independent; identical twiddle values)
__global__ void init_wdft_kernel() {
    int i = blockIdx.x * blockDim.x + threadIdx.x;
    const int n1 = MR * T_;
    if (i < n1) {
        int r = i >> 9, t = i & 511;
        float s, c;
        if (r <= 256) {
            sincospif((float)((r * t) & 511) / 256.0f, &s, &c);
            g_wdft[i] = c;
        } else {
            sincospif((float)(((r - 256) * t) & 511) / 256.0f, &s, &c);
            g_wdft[i] = -s;
        }
    } else {
        int j = i - n1;
        if (j < T_ * KI) {
            int t = j >> 9, c = j & 511;
            float s, cc;
            if (c <= 256) {
                float w = (c == 0 || c == 256) ? (1.f / 512.f) : (2.f / 512.f);
                sincospif((float)((c * t) & 511) / 256.0f, &s, &cc);
                g_widft[j] = w * cc;
            } else {
                int f = c - 256;
                sincospif((float)((f * t) & 511) / 256.0f, &s, &cc);
                g_widft[j] = -(2.f / 512.f) * s;
            }
        }
    }
}

// ---------------- SGEMM v6 (R10 proven) — occupancy cap relaxed to 4 blk/SM ----
#define EPI_NONE    0
#define EPI_PE      2
#define EPI_GELU    3
#define EPI_SIGMASK 4
#define EPI_TMSEL   5
#define EPI_ADDEX   6

// C[M, N] = A[M, K](lda) * B(^T).  K mult of 32, M mult of 64 (per batch).
// BKN=0: B is [N][K] row-major (ldb = row stride), N mult of 32  -> A*B^T
// BKN=1: B is [K][ldb] row-major, logical [K][N]; cols >= ldb read as 0 -> A*B
// blockIdx.z batches: A += z*sA, B += z*sB, C += z*sC.
template <int EPI, int BKN>
__global__ void __launch_bounds__(128, 4) sgemm6_kernel(
        const float* __restrict__ A, int lda, long sA,
        const float* __restrict__ B, int ldb, long sB,
        float* __restrict__ Cm, int ldc, long sC, int N, int K,
        const float* __restrict__ bias,
        const unsigned char* __restrict__ mask,
        const float* __restrict__ token,
        const float* __restrict__ e1, const float* __restrict__ e2,
        const float* __restrict__ e3, const float* __restrict__ e4)
{
    A += (long)blockIdx.z * sA;
    B += (long)blockIdx.z * sB;
    Cm += (long)blockIdx.z * sC;
    __shared__ float As[2][32][64];
    __shared__ float Bs[2][32][32];
    int tid = threadIdx.x;            // 128
    int bm = blockIdx.y * 64;
    int bn = blockIdx.x * 32;
    int tx = (tid & 7) * 4;           // n offset 0..28
    int ty = (tid >> 3) * 4;          // m offset 0..60
    int arow = tid >> 1, akq = (tid & 1) * 16;   // A: 4 quads/thread
    int brow = tid >> 2, bkq = (tid & 3) * 8;    // B^T: 2 quads/thread
    int bkk  = tid >> 2, bnn = (tid & 3) * 8;    // BKN=1 B: 2 quads/thread
    float acc[4][4] = {};
    float4 ra[4], rb[2];

    // prologue: tile 0 -> buffer 0
    #pragma unroll
    for (int j = 0; j < 4; j++)
        ra[j] = *(const float4*)&A[(size_t)(bm + arow) * lda + akq + j * 4];
    if (BKN) {
        #pragma unroll
        for (int j = 0; j < 2; j++) {
            rb[j] = make_float4(0.f, 0.f, 0.f, 0.f);
            if (bn + bnn + j * 4 < ldb)
                rb[j] = *(const float4*)&B[(size_t)bkk * ldb + bn + bnn + j * 4];
        }
    } else {
        #pragma unroll
        for (int j = 0; j < 2; j++)
            rb[j] = *(const float4*)&B[(size_t)(bn + brow) * ldb + bkq + j * 4];
    }
    #pragma unroll
    for (int j = 0; j < 4; j++) {
        As[0][akq + j * 4 + 0][arow] = ra[j].x; As[0][akq + j * 4 + 1][arow] = ra[j].y;
        As[0][akq + j * 4 + 2][arow] = ra[j].z; As[0][akq + j * 4 + 3][arow] = ra[j].w;
    }
    if (BKN) {
        #pragma unroll
        for (int j = 0; j < 2; j++)
            *(float4*)&Bs[0][bkk][bnn + j * 4] = rb[j];
    } else {
        #pragma unroll
        for (int j = 0; j < 2; j++) {
            Bs[0][bkq + j * 4 + 0][brow] = rb[j].x; Bs[0][bkq + j * 4 + 1][brow] = rb[j].y;
            Bs[0][bkq + j * 4 + 2][brow] = rb[j].z; Bs[0][bkq + j * 4 + 3][brow] = rb[j].w;
        }
    }
    __syncthreads();

    int p = 0;
    for (int k0 = 32; ; k0 += 32) {
        bool has_next = (k0 < K);
        if (has_next) {     // prefetch next tile into registers (hidden by compute)
            #pragma unroll
            for (int j = 0; j < 4; j++)
                ra[j] = *(const float4*)&A[(size_t)(bm + arow) * lda + k0 + akq + j * 4];
            if (BKN) {
                #pragma unroll
                for (int j = 0; j < 2; j++) {
                    rb[j] = make_float4(0.f, 0.f, 0.f, 0.f);
                    if (bn + bnn + j * 4 < ldb)
                        rb[j] = *(const float4*)&B[(size_t)(k0 + bkk) * ldb + bn + bnn + j * 4];
                }
            } else {
                #pragma unroll
                for (int j = 0; j < 2; j++)
                    rb[j] = *(const float4*)&B[(size_t)(bn + brow) * ldb + k0 + bkq + j * 4];
            }
        }
        #pragma unroll
        for (int kk = 0; kk < 32; kk++) {
            float4 a = *(const float4*)&As[p][kk][ty];
            float4 b = *(const float4*)&Bs[p][kk][tx];
            float am[4] = {a.x, a.y, a.z, a.w};
            float bv[4] = {b.x, b.y, b.z, b.w};
            #pragma unroll
            for (int i = 0; i < 4; i++)
                #pragma unroll
                for (int j = 0; j < 4; j++)
                    acc[i][j] = fmaf(am[i], bv[j], acc[i][j]);
        }
        if (!has_next) break;
        int q = p ^ 1;
        #pragma unroll
        for (int j = 0; j < 4; j++) {
            As[q][akq + j * 4 + 0][arow] = ra[j].x; As[q][akq + j * 4 + 1][arow] = ra[j].y;
            As[q][akq + j * 4 + 2][arow] = ra[j].z; As[q][akq + j * 4 + 3][arow] = ra[j].w;
        }
        if (BKN) {
            #pragma unroll
            for (int j = 0; j < 2; j++)
                *(float4*)&Bs[q][bkk][bnn + j * 4] = rb[j];
        } else {
            #pragma unroll
            for (int j = 0; j < 2; j++) {
                Bs[q][bkq + j * 4 + 0][brow] = rb[j].x; Bs[q][bkq + j * 4 + 1][brow] = rb[j].y;
                Bs[q][bkq + j * 4 + 2][brow] = rb[j].z; Bs[q][bkq + j * 4 + 3][brow] = rb[j].w;
            }
        }
        __syncthreads();
        p = q;
    }

    const bool vec = ((N & 3) == 0);
    #pragma unroll
    for (int i = 0; i < 4; i++) {
        int row = bm + ty + i;
        float v4[4];
        #pragma unroll
        for (int j = 0; j < 4; j++) {
            int col = bn + tx + j;
            float v = acc[i][j];
            if (EPI == EPI_PE) {
                v += bias[col];
                v += g_pe[(row & (T_ - 1)) * D_ + col];
            } else if (EPI == EPI_GELU) {
                v += bias[col];
                v = 0.5f * v * (1.f + erff(v * 0.70710678118654752f));
            } else if (EPI == EPI_SIGMASK) {
                v += bias[col];
                v = 1.f / (1.f + expf(-v));
                if (mask[row]) v = token[col];
            } else if (EPI == EPI_TMSEL) {
                if (!mask[row]) {
                    float m = v, a = 0.f;
                    for (int dd = 0; dd < D_; dd++) {
                        float u = fmaf(m, e1[dd], e2[dd]);
                        float g = 0.5f * u * (1.f + erff(u * 0.70710678118654752f));
                        a = fmaf(g, e3[dd], a);
                    }
                    v = 1.f / (1.f + expf(-(a + e4[0])));
                }
            } else if (EPI == EPI_ADDEX) {
                // mtd = ex + Wsub@delta  (irfft(rfft(ex)) == ex + masked delta)
                v += g_ex[((long)blockIdx.z * T_ + row) * D_ + col];
            }
            v4[j] = v;
        }
        if (vec) {
            *(float4*)&Cm[(size_t)row * ldc + bn + tx] =
                make_float4(v4[0], v4[1], v4[2], v4[3]);
        } else {
            #pragma unroll
            for (int j = 0; j < 4; j++) {
                int col = bn + tx + j;
                if (col < N) Cm[(size_t)row * ldc + col] = v4[j];
            }
        }
    }
}

// ---------------- windowed-variance score: one block per (b,t) -----------------
__global__ void score_kernel() {
    int bt = blockIdx.x;
    int b = bt >> 9, t = bt & 511;
    int tid = threadIdx.x;            // 256
    int t0 = t - (WIN_ - 1); if (t0 < 0) t0 = 0;
    float denom = (float)((t + 1 < WIN_) ? (t + 1) : WIN_);
    float num = 0.f, den = 0.f;
    for (int d = tid; d < D_; d += 256) {
        float s1 = 0.f, s2 = 0.f;
        const float* p = &g_ex[((size_t)b * T_ + t0) * D_ + d];
        for (int tt = t0; tt <= t; tt++) {
            float v = *p; p += D_;
            s1 += v;
            s2 = fmaf(v, v, s2);
        }
        float m1 = s1 / denom;
        num += s2 / denom - m1 * m1;
        den += m1;
    }
    __shared__ float sn[256], sd[256];
    sn[tid] = num; sd[tid] = den; __syncthreads();
    for (int s = 128; s > 0; s >>= 1) {
        if (tid < s) { sn[tid] += sn[tid + s]; sd[tid] += sd[tid + s]; }
        __syncthreads();
    }
    if (tid == 0) g_score[bt] = sn[0] / (sd[0] + 1e-6f);
}

// ---------------- top-k via rank selection (lax.top_k stable-desc semantics) ---
__global__ void topk_kernel(const float* __restrict__ vals, int n, int k,
                            int* __restrict__ idx_out,
                            unsigned char* __restrict__ mask_out,
                            float* __restrict__ outf)
{
    int b = blockIdx.x;
    int tid = threadIdx.x;            // 512
    __shared__ float v[512];
    for (int i = tid; i < n; i += blockDim.x) v[i] = vals[b * n + i];
    if (tid < n) mask_out[b * n + tid] = 0;
    __syncthreads();
    if (tid < n) {
        float x = v[tid];
        int rank = 0;
        for (int j = 0; j < n; j++) {
            float y = v[j];
            rank += (y > x) || (y == x && j < tid);
        }
        if (rank < k) {
            idx_out[b * k + rank] = tid;
            outf[b * k + rank] = (float)tid;
            mask_out[b * n + tid] = 1;
        }
    }
}

// ---------------- magnitude mean over d: one block per (b,f) -------------------
__global__ void mag_kernel() {
    int bf = blockIdx.x;
    int b = bf / F_, f = bf % F_;
    int d = threadIdx.x;              // 512
    float cr = g_cf[((size_t)b * MR + f) * D_ + d];
    float ci = (f == 0 || f == 256) ? 0.f
             : g_cf[((size_t)b * MR + 256 + f) * D_ + d];
    float m = sqrtf(cr * cr + ci * ci);
    __shared__ float red[512];
    red[d] = m; __syncthreads();
    for (int s = 256; s > 0; s >>= 1) {
        if (d < s) red[d] += red[d + s];
        __syncthreads();
    }
    if (d == 0) g_mag[bf] = red[0] * (1.f / 512.f);
}

// ---------------- fused: freq top-k + tm mask + compacted masked-row list ------
__global__ void freqpost_kernel(float* __restrict__ out_fidx) {
    int b = blockIdx.x;
    int tid = threadIdx.x;            // 512
    __shared__ float v[512];
    if (tid < F_) v[tid] = g_mag[b * F_ + tid];
    if (tid < F_) g_fmask[b * F_ + tid] = 0;
    if (tid < NDELTA) g_rowlist[b * NDELTA + tid] = -1;
    __syncthreads();
    if (tid < F_) {
        float x = v[tid];
        int rank = 0;
        for (int j = 0; j < F_; j++) {
            float y = v[j];
            rank += (y > x) || (y == x && j < tid);
        }
        if (rank < K_TOP) {
            g_fidx[b * K_TOP + rank] = tid;
            out_fidx[b * K_TOP + rank] = (float)tid;
            g_fmask[b * F_ + tid] = 1;
        }
    }
    __syncthreads();
    {
        const unsigned char* fm = &g_fmask[b * F_];
        int t = tid;
        float y = fm[0] ? 1.f : 0.f;
        for (int f = 1; f < 256; f++)
            if (fm[f]) y += 2.f * g_costab[(f * t) & 511];
        if (fm[256]) y += (t & 1) ? -1.f : 1.f;
        g_tm[b * T_ + t] = (y != 0.f) ? 1 : 0;
    }
    if (tid < F_ && g_fmask[b * F_ + tid]) {
        int f = tid;
        int rank = 0;
        for (int g2 = 0; g2 < f; g2++)
            if (g_fmask[b * F_ + g2]) rank += (g2 == 0 || g2 == 256) ? 1 : 2;
        g_rowlist[b * NDELTA + rank] = f;               // re row
        if (f >= 1 && f <= 255)
            g_rowlist[b * NDELTA + rank + 1] = 256 + f; // im row
    }
}

// ---------------- build delta (token - cf, masked rows) + gathered Widft cols --
__global__ void builddw_kernel(const float* __restrict__ f_tok_re,
                               const float* __restrict__ f_tok_im) {
    int i = blockIdx.x * blockDim.x + threadIdx.x;
    const int nD = B_ * NDELTA * D_;
    if (i < nD) {
        int b = i / (NDELTA * D_);
        int rem = i - b * NDELTA * D_;
        int j = rem >> 9, d = rem & 511;
        int r = g_rowlist[b * NDELTA + j];
        float v = 0.f;
        if (r >= 0) {
            float tok = (r <= 256) ? f_tok_re[d] : f_tok_im[d];
            v = tok - g_cf[((size_t)b * MR + r) * D_ + d];
        }
        g_delta[i] = v;
    } else {
        int k = i - nD;
        if (k < B_ * T_ * NDELTA) {
            int b = k / (T_ * NDELTA);
            int rem = k - b * T_ * NDELTA;
            int t = rem / NDELTA, j = rem % NDELTA;
            int r = g_rowlist[b * NDELTA + j];
            g_wsub[k] = (r >= 0) ? g_widft[t * KI + r] : 0.f;
        }
    }
}

// ---------------- launch ----------------
extern "C" void kernel_launch(void* const* d_in, const int* in_sizes, int n_in,
                              void* d_out, int out_size) {
    const float* x        = (const float*)d_in[0];
    const float* W_emb    = (const float*)d_in[1];
    const float* b_emb    = (const float*)d_in[2];
    const float* t_token  = (const float*)d_in[3];
    const float* tW1      = (const float*)d_in[4];
    const float* tb1      = (const float*)d_in[5];
    const float* tW2      = (const float*)d_in[6];
    const float* tb2      = (const float*)d_in[7];
    const float* f_tok_re = (const float*)d_in[8];
    const float* f_tok_im = (const float*)d_in[9];
    const float* fW1      = (const float*)d_in[10];
    const float* fb1      = (const float*)d_in[11];
    const float* fW2      = (const float*)d_in[12];
    const float* fb2      = (const float*)d_in[13];
    float* out = (float*)d_out;

    // output packing: out_t [B,T,D] | tidx [B,51] | out_f [B,T,C] | fidx [B,51]
    float* out_t    = out;
    float* out_tidx = out + (size_t)B_ * T_ * D_;
    float* out_f    = out_tidx + B_ * K_TOP;
    float* out_fidx = out_f + (size_t)B_ * T_ * C_;

    float *p_ex, *p_h, *p_mtd, *p_score, *p_xpad, *p_wpad;
    float *p_wdft, *p_widft, *p_cf, *p_delta, *p_wsub;
    int *p_tidx;
    unsigned char *p_tmask, *p_tm;
    cudaGetSymbolAddress((void**)&p_ex,    g_ex);
    cudaGetSymbolAddress((void**)&p_h,     g_h);
    cudaGetSymbolAddress((void**)&p_mtd,   g_mtd);
    cudaGetSymbolAddress((void**)&p_score, g_score);
    cudaGetSymbolAddress((void**)&p_xpad,  g_xpad);
    cudaGetSymbolAddress((void**)&p_wpad,  g_wpad);
    cudaGetSymbolAddress((void**)&p_wdft,  g_wdft);
    cudaGetSymbolAddress((void**)&p_widft, g_widft);
    cudaGetSymbolAddress((void**)&p_cf,    g_cf);
    cudaGetSymbolAddress((void**)&p_delta, g_delta);
    cudaGetSymbolAddress((void**)&p_wsub,  g_wsub);
    cudaGetSymbolAddress((void**)&p_tidx,  g_tidx);
    cudaGetSymbolAddress((void**)&p_tmask, g_tmask);
    cudaGetSymbolAddress((void**)&p_tm,    g_tm);

    if (!g_sB) {
        cudaStreamCreateWithFlags(&g_sB, cudaStreamNonBlocking);
        cudaStreamCreateWithFlags(&g_sC, cudaStreamNonBlocking);
        cudaEventCreateWithFlags(&g_evStart, cudaEventDisableTiming);
        cudaEventCreateWithFlags(&g_evFork, cudaEventDisableTiming);
        cudaEventCreateWithFlags(&g_evJoin, cudaEventDisableTiming);
        cudaEventCreateWithFlags(&g_evC, cudaEventDisableTiming);
    }

    // ---- legal capture fork at t=0 ----
    cudaEventRecord(g_evStart, 0);
    cudaStreamWaitEvent(g_sB, g_evStart, 0);

    // DFT weight tables on g_sB (input-independent; overlaps prologue + GEMM1)
    init_wdft_kernel<<<(MR * T_ + T_ * KI + 255) / 256, 256, 0, g_sB>>>();

    // ---- prologue on stream 0 ----
    init_div_kernel<<<1, 512>>>();
    prep_kernel<<<(T_ * D_ + (B_ * T_ + D_) * KPAD + 255) / 256, 256>>>(x, W_emb);

    // ex = x * W_emb^T + b_emb + PE      (padded K=288)
    sgemm6_kernel<EPI_PE, 0><<<dim3(D_ / 32, B_ * T_ / 64), 128>>>(
        p_xpad, KPAD, 0, p_wpad, KPAD, 0, p_ex, D_, 0, D_, KPAD,
        b_emb, nullptr, nullptr, nullptr, nullptr, nullptr, nullptr);

    // ---- fork after ex ----
    cudaEventRecord(g_evFork, 0);
    cudaStreamWaitEvent(g_sB, g_evFork, 0);
    cudaStreamWaitEvent(g_sC, g_evFork, 0);

    // ---- path C: score + temporal top-k (overlaps h-GEMM) ----
    score_kernel<<<B_ * T_, 256, 0, g_sC>>>();
    topk_kernel<<<B_, 512, 0, g_sC>>>(p_score, T_, K_TOP, p_tidx, p_tmask, out_tidx);
    cudaEventRecord(g_evC, g_sC);

    // ---- path B (frequency) on g_sB ----
    {
        // cf[b] = Wdft[512,512] @ ex[b][512,512]   (packed re/im rows)
        sgemm6_kernel<EPI_NONE, 1><<<dim3(D_ / 32, MR / 64, B_), 128, 0, g_sB>>>(
            p_wdft, T_, 0, p_ex, D_, (long)T_ * D_, p_cf, D_, (long)MR * D_, D_, T_,
            nullptr, nullptr, nullptr, nullptr, nullptr, nullptr, nullptr);
        mag_kernel<<<B_ * F_, 512, 0, g_sB>>>();
        freqpost_kernel<<<B_, 512, 0, g_sB>>>(out_fidx);
        builddw_kernel<<<(B_ * NDELTA * D_ + B_ * T_ * NDELTA + 255) / 256, 256, 0, g_sB>>>(
            f_tok_re, f_tok_im);
        // mtd[b] = ex[b] + Wsub[b][512,128] @ delta[b][128,512]
        sgemm6_kernel<EPI_ADDEX, 1><<<dim3(D_ / 32, T_ / 64, B_), 128, 0, g_sB>>>(
            p_wsub, NDELTA, (long)T_ * NDELTA,
            p_delta, D_, (long)NDELTA * D_,
            p_mtd, D_, (long)T_ * D_, D_, NDELTA,
            nullptr, nullptr, nullptr, nullptr, nullptr, nullptr, nullptr);
        // out_f = tmsel(mtd @ W_emb)   (fused mx + outf)
        sgemm6_kernel<EPI_TMSEL, 1><<<dim3((C_ + 31) / 32, B_ * T_ / 64), 128, 0, g_sB>>>(
            p_mtd, D_, 0, p_wpad, KPAD, 0, out_f, C_, 0, C_, D_,
            nullptr, p_tm, nullptr, fW1, fb1, fW2, fb2);
        cudaEventRecord(g_evJoin, g_sB);
    }

    // ---- path A (temporal GEMMs) on stream 0 ----
    // h = gelu(ex * tW1^T + tb1)   — independent of score/topk
    sgemm6_kernel<EPI_GELU, 0><<<dim3(D_ / 32, B_ * T_ / 64), 128>>>(
        p_ex, D_, 0, tW1, D_, 0, p_h, D_, 0, D_, D_,
        tb1, nullptr, nullptr, nullptr, nullptr, nullptr, nullptr);
    // out_t = tmask ? t_token : sigmoid(h * tW2^T + tb2)  — needs tmask from path C
    cudaStreamWaitEvent(0, g_evC, 0);
    sgemm6_kernel<EPI_SIGMASK, 0><<<dim3(D_ / 32, B_ * T_ / 64), 128>>>(
        p_h, D_, 0, tW2, D_, 0, out_t, D_, 0, D_, D_,
        tb2, p_tmask, t_token, nullptr, nullptr, nullptr, nullptr);

    // ---- join ----
    cudaStreamWaitEvent(0, g_evJoin, 0);
}